// round 11
// baseline (speedup 1.0000x reference)
#include <cuda_runtime.h>
#include <cuda_fp16.h>
#include <cstdint>

// Problem-shape upper bounds (this problem: N=100000, E=1600000, E+N=1700000)
#define MAXN 100000
#define MAXE 1700000

// ---------------- device scratch (static, allocation-free) ----------------
__device__ float g_h1f[(size_t)MAXN * 64];     // layer-1 features, fp32
__device__ float g_as1[MAXN];                  // per-node a_src (layer 1)
__device__ float g_ad1[MAXN];                  // per-node a_dst (layer 1)
__device__ float4 g_node2[MAXN];               // {h3_0, h3_1, a_src2, a_dst2}
__device__ int2  g_sedge[MAXE];                // dst-sorted {src, attr_bits}
__device__ int   g_deg[MAXN];
__device__ int   g_start[MAXN + 1];
__device__ int   g_cursor[MAXN];
__device__ float g_partial[512];               // per-block partial sums of edge_attr
__device__ float g_scal[6];                    // {c1, -, c2, -, mean_ea, -}

// ---------------- f32x2 packed-FMA helpers (Blackwell FFMA2) ----------------
__device__ __forceinline__ unsigned long long pack2(float lo, float hi) {
    unsigned long long r;
    asm("mov.b64 %0, {%1,%2};" : "=l"(r)
        : "r"(__float_as_uint(lo)), "r"(__float_as_uint(hi)));
    return r;
}
__device__ __forceinline__ void fma2(unsigned long long& d,
                                     unsigned long long a, unsigned long long b) {
    asm("fma.rn.f32x2 %0, %1, %2, %0;" : "+l"(d) : "l"(a), "l"(b));
}
__device__ __forceinline__ float2 unpack2(unsigned long long v) {
    unsigned lo, hi;
    asm("mov.b64 {%0,%1}, %2;" : "=r"(lo), "=r"(hi) : "l"(v));
    return make_float2(__uint_as_float(lo), __uint_as_float(hi));
}

// ---------------- prehist: partial sums of edge_attr + dst-degree histogram ----------
// grid MUST be 512 x 256 (g_partial sized for 512 blocks); g_deg pre-zeroed by memset.
__global__ void prehist_kernel(const float* __restrict__ ea, int nea,
                               const int* __restrict__ ei, int E) {
    const int t = blockIdx.x * blockDim.x + threadIdx.x;
    const int stride = 512 * 256;
    float s = 0.f;
    for (int i = t; i < nea; i += stride) s += ea[i];
    #pragma unroll
    for (int o = 16; o; o >>= 1) s += __shfl_xor_sync(0xffffffffu, s, o);
    __shared__ float sdata[8];
    if ((threadIdx.x & 31) == 0) sdata[threadIdx.x >> 5] = s;
    __syncthreads();
    if (threadIdx.x < 8) {
        float v = sdata[threadIdx.x];
        #pragma unroll
        for (int o = 4; o; o >>= 1) v += __shfl_xor_sync(0xffu, v, o);
        if (threadIdx.x == 0) g_partial[blockIdx.x] = v;
    }
    const int e4 = E >> 2;
    for (int i = t; i < e4; i += stride) {
        int4 d4 = *(const int4*)&ei[E + i * 4];
        atomicAdd(&g_deg[d4.x], 1);
        atomicAdd(&g_deg[d4.y], 1);
        atomicAdd(&g_deg[d4.z], 1);
        atomicAdd(&g_deg[d4.w], 1);
    }
    if (t < (E & 3)) atomicAdd(&g_deg[ei[E + e4 * 4 + t]], 1);
}

// ---------------- single-block: ea-mean + scalars, exclusive scan over (deg+1) -------
// Reserves slot start[i] for node i's self-loop: cursor starts at start[i]+1.
__global__ void __launch_bounds__(1024) scan_kernel(const float* __restrict__ We1,
                                                    const float* __restrict__ ae1,
                                                    const float* __restrict__ We2,
                                                    const float* __restrict__ ae2,
                                                    int H, int C, float invE, int N) {
    __shared__ int sh[1024];
    __shared__ float sf[16];
    const int tid = threadIdx.x;
    if (tid < 512) {
        float v = g_partial[tid];
        #pragma unroll
        for (int o = 16; o; o >>= 1) v += __shfl_xor_sync(0xffffffffu, v, o);
        if ((tid & 31) == 0) sf[tid >> 5] = v;
    }
    __syncthreads();
    if (tid == 0) {
        float tot = 0.f;
        #pragma unroll
        for (int k = 0; k < 16; k++) tot += sf[k];
        float c1 = 0.f;
        for (int k = 0; k < H; k++) c1 += We1[k] * ae1[k];
        float c2 = 0.f;
        for (int k = 0; k < C; k++) c2 += We2[k] * ae2[k];
        g_scal[0] = c1;
        g_scal[2] = c2;
        g_scal[4] = tot * invE;   // mean edge attr (self-loop fill value)
    }
    __syncthreads();
    const int chunk = (((N + 1023) / 1024) + 3) & ~3;   // multiple of 4
    const int b = tid * chunk;
    const int e = min(b + chunk, N);
    int s = 0;
    if (b < N) {
        int i = b;
        for (; i + 3 < e; i += 4) {
            int4 v = *(const int4*)&g_deg[i];
            s += v.x + v.y + v.z + v.w + 4;
        }
        for (; i < e; i++) s += g_deg[i] + 1;
    }
    sh[tid] = s;
    __syncthreads();
    #pragma unroll
    for (int off = 1; off < 1024; off <<= 1) {
        int v = (tid >= off) ? sh[tid - off] : 0;
        __syncthreads();
        sh[tid] += v;
        __syncthreads();
    }
    if (b < N) {
        int run = (tid > 0) ? sh[tid - 1] : 0;
        int i = b;
        for (; i + 3 < e; i += 4) {
            int4 v = *(const int4*)&g_deg[i];
            int4 st = make_int4(run,
                                run + v.x + 1,
                                run + v.x + v.y + 2,
                                run + v.x + v.y + v.z + 3);
            *(int4*)&g_start[i] = st;
            int4 cu = make_int4(st.x + 1, st.y + 1, st.z + 1, st.w + 1);
            *(int4*)&g_cursor[i] = cu;
            run += v.x + v.y + v.z + v.w + 4;
        }
        for (; i < e; i++) {
            g_start[i] = run; g_cursor[i] = run + 1;
            run += g_deg[i] + 1;
        }
        if (e == N) g_start[N] = run;
    }
}

// ---------------- scatter edges into dst-sorted order (8 edges/thread) ---------------
// Self-loops go into the reserved slot start[i] with a PLAIN store (no atomic).
__global__ void sort_kernel(const int* __restrict__ ei, const float* __restrict__ ea,
                            int E, int N) {
    int t = blockIdx.x * blockDim.x + threadIdx.x;
    int eB = (E + 7) >> 3;
    int nB = (N + 3) >> 2;
    if (t < eB) {
        int q = t * 8;
        if (q + 7 < E && ((E & 7) == 0)) {
            int4 sa = *(const int4*)&ei[q];
            int4 sb = *(const int4*)&ei[q + 4];
            int4 da = *(const int4*)&ei[E + q];
            int4 db = *(const int4*)&ei[E + q + 4];
            float4 aa = *(const float4*)&ea[q];
            float4 ab = *(const float4*)&ea[q + 4];
            int p0 = atomicAdd(&g_cursor[da.x], 1);
            int p1 = atomicAdd(&g_cursor[da.y], 1);
            int p2 = atomicAdd(&g_cursor[da.z], 1);
            int p3 = atomicAdd(&g_cursor[da.w], 1);
            int p4 = atomicAdd(&g_cursor[db.x], 1);
            int p5 = atomicAdd(&g_cursor[db.y], 1);
            int p6 = atomicAdd(&g_cursor[db.z], 1);
            int p7 = atomicAdd(&g_cursor[db.w], 1);
            g_sedge[p0] = make_int2(sa.x, __float_as_int(aa.x));
            g_sedge[p1] = make_int2(sa.y, __float_as_int(aa.y));
            g_sedge[p2] = make_int2(sa.z, __float_as_int(aa.z));
            g_sedge[p3] = make_int2(sa.w, __float_as_int(aa.w));
            g_sedge[p4] = make_int2(sb.x, __float_as_int(ab.x));
            g_sedge[p5] = make_int2(sb.y, __float_as_int(ab.y));
            g_sedge[p6] = make_int2(sb.z, __float_as_int(ab.z));
            g_sedge[p7] = make_int2(sb.w, __float_as_int(ab.w));
        } else {
            for (int k = 0; k < 8 && q + k < E; k++) {
                int d = ei[E + q + k];
                int pos = atomicAdd(&g_cursor[d], 1);
                g_sedge[pos] = make_int2(ei[q + k], __float_as_int(ea[q + k]));
            }
        }
    } else if (t < eB + nB) {
        int i0 = (t - eB) * 4;
        float mean = g_scal[4];
        int4 st = *(const int4*)&g_start[i0];   // i0 is 4-aligned by construction
        int sarr[4] = {st.x, st.y, st.z, st.w};
        for (int k = 0; k < 4 && i0 + k < N; k++)
            g_sedge[sarr[k]] = make_int2(i0 + k, __float_as_int(mean));
    }
}

// ---------------- SGEMM: h1 = x[M,128] @ W1[128,64] ----------------
// FFMA2 inner with M-dim pairing; fp32 output + fused attention logits.
__global__ void __launch_bounds__(256) gemm1_kernel(const float* __restrict__ x,
                                                    const float* __restrict__ W,
                                                    const float* __restrict__ att_s,
                                                    const float* __restrict__ att_d, int M) {
    __shared__ float Xs[16][128];
    __shared__ float Ws[16][64];
    const int tid = threadIdx.x;
    const int tr = tid >> 4;        // 0..15 -> 8 rows each
    const int tc = tid & 15;        // 0..15 -> 4 cols each
    const int m0 = blockIdx.x * 128;
    unsigned long long accp[4][4];  // [col j][row-pair p] -> rows 2p,2p+1
    #pragma unroll
    for (int j = 0; j < 4; j++)
        #pragma unroll
        for (int p = 0; p < 4; p++) accp[j][p] = 0ull;

    for (int k0 = 0; k0 < 128; k0 += 16) {
        #pragma unroll
        for (int it = 0; it < 2; it++) {
            int f = it * 256 + tid;           // 0..511
            int row = f >> 2;
            int kq = (f & 3) * 4;
            float4 v = make_float4(0.f, 0.f, 0.f, 0.f);
            int gr = m0 + row;
            if (gr < M) v = *(const float4*)&x[(size_t)gr * 128 + k0 + kq];
            Xs[kq + 0][row] = v.x; Xs[kq + 1][row] = v.y;
            Xs[kq + 2][row] = v.z; Xs[kq + 3][row] = v.w;
        }
        {
            int kk = tid >> 4;
            int c4 = (tid & 15) * 4;
            *(float4*)&Ws[kk][c4] = *(const float4*)&W[(size_t)(k0 + kk) * 64 + c4];
        }
        __syncthreads();
        #pragma unroll
        for (int kk = 0; kk < 16; kk++) {
            unsigned long long ap[4];
            #pragma unroll
            for (int p = 0; p < 4; p++)
                ap[p] = *(const unsigned long long*)&Xs[kk][tr * 8 + 2 * p];
            float4 bv = *(const float4*)&Ws[kk][tc * 4];
            unsigned long long bd0 = pack2(bv.x, bv.x);
            unsigned long long bd1 = pack2(bv.y, bv.y);
            unsigned long long bd2 = pack2(bv.z, bv.z);
            unsigned long long bd3 = pack2(bv.w, bv.w);
            #pragma unroll
            for (int p = 0; p < 4; p++) {
                fma2(accp[0][p], ap[p], bd0);
                fma2(accp[1][p], ap[p], bd1);
                fma2(accp[2][p], ap[p], bd2);
                fma2(accp[3][p], ap[p], bd3);
            }
        }
        __syncthreads();
    }
    float acc[8][4];
    #pragma unroll
    for (int j = 0; j < 4; j++)
        #pragma unroll
        for (int p = 0; p < 4; p++) {
            float2 pr = unpack2(accp[j][p]);
            acc[2 * p][j] = pr.x;
            acc[2 * p + 1][j] = pr.y;
        }
    #pragma unroll
    for (int i = 0; i < 8; i++) {
        int gr = m0 + tr * 8 + i;
        if (gr < M) {
            *(float4*)&g_h1f[(size_t)gr * 64 + tc * 4] =
                make_float4(acc[i][0], acc[i][1], acc[i][2], acc[i][3]);
        }
    }
    // fused per-row attention logits: reduce across the 16 tc lanes
    float4 asv = *(const float4*)&att_s[tc * 4];
    float4 adv = *(const float4*)&att_d[tc * 4];
    #pragma unroll
    for (int i = 0; i < 8; i++) {
        float pas = acc[i][0] * asv.x + acc[i][1] * asv.y + acc[i][2] * asv.z + acc[i][3] * asv.w;
        float pad = acc[i][0] * adv.x + acc[i][1] * adv.y + acc[i][2] * adv.z + acc[i][3] * adv.w;
        #pragma unroll
        for (int o = 8; o; o >>= 1) {
            pas += __shfl_xor_sync(0xffffffffu, pas, o);
            pad += __shfl_xor_sync(0xffffffffu, pad, o);
        }
        if (tc == 0) {
            int gr = m0 + tr * 8 + i;
            if (gr < M) { g_as1[gr] = pas; g_ad1[gr] = pad; }
        }
    }
}

// ---------------- layer-1 aggregation: 4 nodes/warp, fp32 f32x2 FMA ------------------
// Each lane handles 8 features (32B = 2x LDG.128, halves are ready f32x2 pairs).
// w computed per lane (1 exp per edge total) and circulated via width-8 shuffles.
__global__ void aggr1_kernel(const float* __restrict__ bias1, const float* __restrict__ W2,
                             const float* __restrict__ as2, const float* __restrict__ ad2,
                             int N) {
    int gwarp = (blockIdx.x * blockDim.x + threadIdx.x) >> 5;
    int lane = threadIdx.x & 31;
    int g = lane & 7;                     // position within the 8-lane node group
    int node = gwarp * 4 + (lane >> 3);
    bool valid = node < N;
    const unsigned gmask = 0xFFu << (lane & 24);   // this group's 8 lanes
    const float c1 = g_scal[0];
    const int beg = valid ? g_start[node] : 0;
    const int end = valid ? g_start[node + 1] : 0;
    const float add = valid ? g_ad1[node] : 0.f;
    unsigned long long acc0 = 0ull, acc1 = 0ull, acc2 = 0ull, acc3 = 0ull;
    float dsum = 0.f;
    int i = beg;
    for (; i + 8 <= end; i += 8) {
        int2 eg = g_sedge[i + g];          // coalesced: 8 lanes cover 64B
        float lg = g_as1[eg.x] + add + __int_as_float(eg.y) * c1;
        lg = lg > 0.f ? lg : 0.2f * lg;
        float wg = __expf(lg);
        #pragma unroll
        for (int j = 0; j < 8; j++) {
            int   sj = __shfl_sync(gmask, eg.x, j, 8);
            float wj = __shfl_sync(gmask, wg, j, 8);
            unsigned long long wp = pack2(wj, wj);
            const ulonglong2* p = (const ulonglong2*)&g_h1f[(size_t)sj * 64 + 8 * g];
            ulonglong2 hA = p[0];
            ulonglong2 hB = p[1];
            fma2(acc0, hA.x, wp);
            fma2(acc1, hA.y, wp);
            fma2(acc2, hB.x, wp);
            fma2(acc3, hB.y, wp);
            dsum += wj;
        }
    }
    {
        int rem = end - i;
        if (rem > 0) {
            int2 eg = (g < rem) ? g_sedge[i + g] : make_int2(0, 0);
            float wg = 0.f;
            if (g < rem) {
                float lg = g_as1[eg.x] + add + __int_as_float(eg.y) * c1;
                lg = lg > 0.f ? lg : 0.2f * lg;
                wg = __expf(lg);
            }
            for (int j = 0; j < rem; j++) {
                int   sj = __shfl_sync(gmask, eg.x, j, 8);
                float wj = __shfl_sync(gmask, wg, j, 8);
                unsigned long long wp = pack2(wj, wj);
                const ulonglong2* p = (const ulonglong2*)&g_h1f[(size_t)sj * 64 + 8 * g];
                ulonglong2 hA = p[0];
                ulonglong2 hB = p[1];
                fma2(acc0, hA.x, wp);
                fma2(acc1, hA.y, wp);
                fma2(acc2, hB.x, wp);
                fma2(acc3, hB.y, wp);
                dsum += wj;
            }
        }
    }
    float2 a0 = unpack2(acc0), a1 = unpack2(acc1);
    float2 a2 = unpack2(acc2), a3 = unpack2(acc3);
    float inv = 1.f / (dsum + 1e-16f);
    // fused: bias + relu + W2 projection + layer-2 logit coefficients
    float4 ba = *(const float4*)&bias1[g * 8];
    float4 bb = *(const float4*)&bias1[g * 8 + 4];
    float v0 = fmaxf(a0.x * inv + ba.x, 0.f);
    float v1 = fmaxf(a0.y * inv + ba.y, 0.f);
    float v2 = fmaxf(a1.x * inv + ba.z, 0.f);
    float v3 = fmaxf(a1.y * inv + ba.w, 0.f);
    float v4 = fmaxf(a2.x * inv + bb.x, 0.f);
    float v5 = fmaxf(a2.y * inv + bb.y, 0.f);
    float v6 = fmaxf(a3.x * inv + bb.z, 0.f);
    float v7 = fmaxf(a3.y * inv + bb.w, 0.f);
    // W2 rows g*8 .. g*8+7 of [64,2]
    float4 wa = *(const float4*)&W2[g * 16];
    float4 wb = *(const float4*)&W2[g * 16 + 4];
    float4 wc = *(const float4*)&W2[g * 16 + 8];
    float4 wd = *(const float4*)&W2[g * 16 + 12];
    float s0 = v0 * wa.x + v1 * wa.z + v2 * wb.x + v3 * wb.z
             + v4 * wc.x + v5 * wc.z + v6 * wd.x + v7 * wd.z;
    float s1 = v0 * wa.y + v1 * wa.w + v2 * wb.y + v3 * wb.w
             + v4 * wc.y + v5 * wc.w + v6 * wd.y + v7 * wd.w;
    // all 32 lanes reach here (no early return) -> full-warp-safe xor reduce within groups
    #pragma unroll
    for (int o = 4; o; o >>= 1) {
        s0 += __shfl_xor_sync(0xffffffffu, s0, o);
        s1 += __shfl_xor_sync(0xffffffffu, s1, o);
    }
    if (valid && g == 0) {
        g_node2[node] = make_float4(s0, s1,
                                    s0 * as2[0] + s1 * as2[1],
                                    s0 * ad2[0] + s1 * ad2[1]);
    }
}

// ---------------- layer-2 aggregation + log_softmax (8 lanes/node, 2-way unroll) -----
__global__ void aggr2_kernel(const float* __restrict__ bias2, float* __restrict__ out, int N) {
    int t = blockIdx.x * blockDim.x + threadIdx.x;
    int node = t >> 3;
    int sub = t & 7;
    bool valid = node < N;
    const float c2 = g_scal[2];
    const float add = valid ? g_node2[node].w : 0.f;
    const int beg = valid ? g_start[node] : 0;
    const int end = valid ? g_start[node + 1] : 0;
    float a0 = 0.f, a1 = 0.f, ds = 0.f;
    int i = beg + sub;
    while (i + 8 < end) {
        int2 eA = g_sedge[i];
        int2 eB = g_sedge[i + 8];
        float atA = __int_as_float(eA.y);
        float atB = __int_as_float(eB.y);
        float4 nA = g_node2[eA.x];
        float4 nB = g_node2[eB.x];
        float lgA = nA.z + add + atA * c2; lgA = lgA > 0.f ? lgA : 0.2f * lgA;
        float lgB = nB.z + add + atB * c2; lgB = lgB > 0.f ? lgB : 0.2f * lgB;
        float wA = __expf(lgA), wB = __expf(lgB);
        a0 += wA * nA.x + wB * nB.x;
        a1 += wA * nA.y + wB * nB.y;
        ds += wA + wB;
        i += 16;
    }
    if (i < end) {
        int2 eA = g_sedge[i];
        float atA = __int_as_float(eA.y);
        float4 nA = g_node2[eA.x];
        float lgA = nA.z + add + atA * c2; lgA = lgA > 0.f ? lgA : 0.2f * lgA;
        float wA = __expf(lgA);
        a0 += wA * nA.x; a1 += wA * nA.y; ds += wA;
    }
    #pragma unroll
    for (int o = 1; o <= 4; o <<= 1) {
        a0 += __shfl_xor_sync(0xffffffffu, a0, o);
        a1 += __shfl_xor_sync(0xffffffffu, a1, o);
        ds += __shfl_xor_sync(0xffffffffu, ds, o);
    }
    if (valid && sub == 0) {
        float inv = 1.f / (ds + 1e-16f);
        float o0 = a0 * inv + bias2[0];
        float o1 = a1 * inv + bias2[1];
        float m = fmaxf(o0, o1);
        float z = logf(expf(o0 - m) + expf(o1 - m));
        out[2 * node] = o0 - m - z;
        out[2 * node + 1] = o1 - m - z;
    }
}

// ---------------- host launcher ----------------
extern "C" void kernel_launch(void* const* d_in, const int* in_sizes, int n_in,
                              void* d_out, int out_size) {
    const float* x   = (const float*)d_in[0];
    const int*   ei  = (const int*)d_in[1];
    const float* ea  = (const float*)d_in[2];
    const float* W1  = (const float*)d_in[3];
    const float* as1 = (const float*)d_in[4];
    const float* ad1 = (const float*)d_in[5];
    const float* We1 = (const float*)d_in[6];
    const float* ae1 = (const float*)d_in[7];
    const float* b1  = (const float*)d_in[8];
    const float* W2  = (const float*)d_in[9];
    const float* as2 = (const float*)d_in[10];
    const float* ad2 = (const float*)d_in[11];
    const float* We2 = (const float*)d_in[12];
    const float* ae2 = (const float*)d_in[13];
    const float* b2  = (const float*)d_in[14];
    float* out = (float*)d_out;

    const int H   = in_sizes[4];          // 64
    const int Fin = in_sizes[3] / H;      // 128
    const int N   = in_sizes[0] / Fin;    // 100000
    const int E   = in_sizes[1] / 2;      // 1600000
    const int C   = in_sizes[10];         // 2
    const int nea = in_sizes[2];          // E * ED

    const int T = 256;
    const int eB = (E + 7) >> 3;
    const int nB = (N + 3) >> 2;

    void* deg_ptr = nullptr;
    cudaGetSymbolAddress(&deg_ptr, g_deg);

    // Fork: the ENTIRE preprocessing + CSR-sort pipeline is independent of the
    // GEMM (w computed inside aggr1), so it all overlaps on a side stream.
    cudaStream_t s_pre;
    cudaEvent_t ev_fork, ev_join;
    cudaStreamCreateWithFlags(&s_pre, cudaStreamNonBlocking);
    cudaEventCreateWithFlags(&ev_fork, cudaEventDisableTiming);
    cudaEventCreateWithFlags(&ev_join, cudaEventDisableTiming);

    cudaEventRecord(ev_fork, 0);
    cudaStreamWaitEvent(s_pre, ev_fork, 0);

    // side stream: memset(deg) -> prehist -> scan(+scalars) -> sort
    cudaMemsetAsync(deg_ptr, 0, (size_t)N * sizeof(int), s_pre);
    prehist_kernel<<<512, T, 0, s_pre>>>(ea, nea, ei, E);
    scan_kernel<<<1, 1024, 0, s_pre>>>(We1, ae1, We2, ae2, H, C, 1.0f / (float)E, N);
    sort_kernel<<<(eB + nB + T - 1) / T, T, 0, s_pre>>>(ei, ea, E, N);
    cudaEventRecord(ev_join, s_pre);

    // main stream: gemm runs concurrently with the whole chain above
    gemm1_kernel<<<(N + 127) / 128, 256>>>(x, W1, as1, ad1, N);

    cudaStreamWaitEvent((cudaStream_t)0, ev_join, 0);

    aggr1_kernel<<<((N + 3) / 4 * 32 + T - 1) / T, T>>>(b1, W2, as2, ad2, N);
    aggr2_kernel<<<(N * 8 + T - 1) / T, T>>>(b2, out, N);

    cudaEventDestroy(ev_fork);
    cudaEventDestroy(ev_join);
    cudaStreamDestroy(s_pre);
}

// round 12
// speedup vs baseline: 1.1742x; 1.1742x over previous
#include <cuda_runtime.h>
#include <cuda_fp16.h>
#include <cstdint>

// Problem-shape upper bounds (this problem: N=100000, E=1600000, E+N=1700000)
#define MAXN 100000
#define MAXE 1700000

// ---------------- device scratch (static, allocation-free) ----------------
__device__ __half2 g_h1h[(size_t)MAXN * 32];   // layer-1 features, fp16 (64 per node)
__device__ float g_as1[MAXN];                  // per-node a_src (layer 1)
__device__ float g_ad1[MAXN];                  // per-node a_dst (layer 1)
__device__ float4 g_node2[MAXN];               // {h3_0, h3_1, a_src2, a_dst2}
__device__ int2  g_sedge[MAXE];                // dst-sorted {src, attr_bits}
__device__ int   g_deg[MAXN];
__device__ int   g_start[MAXN + 1];
__device__ int   g_cursor[MAXN];
__device__ float g_partial[512];               // per-block partial sums of edge_attr
__device__ float g_scal[6];                    // {c1, -, c2, -, mean_ea, -}

// ---------------- tf32 helpers ----------------
__device__ __forceinline__ uint32_t f2tf32(float f) {
    uint32_t r;
    asm("cvt.rna.tf32.f32 %0, %1;" : "=r"(r) : "f"(f));
    return r;
}
__device__ __forceinline__ void mma_tf32(float d[4], uint32_t a0, uint32_t a1,
                                         uint32_t a2, uint32_t a3,
                                         uint32_t b0, uint32_t b1) {
    asm("mma.sync.aligned.m16n8k8.row.col.f32.tf32.tf32.f32 "
        "{%0,%1,%2,%3}, {%4,%5,%6,%7}, {%8,%9}, {%0,%1,%2,%3};"
        : "+f"(d[0]), "+f"(d[1]), "+f"(d[2]), "+f"(d[3])
        : "r"(a0), "r"(a1), "r"(a2), "r"(a3), "r"(b0), "r"(b1));
}

// ---------------- prehist: partial sums of edge_attr + dst-degree histogram ----------
// grid MUST be 512 x 256 (g_partial sized for 512 blocks); g_deg pre-zeroed by memset.
__global__ void prehist_kernel(const float* __restrict__ ea, int nea,
                               const int* __restrict__ ei, int E) {
    const int t = blockIdx.x * blockDim.x + threadIdx.x;
    const int stride = 512 * 256;
    float s = 0.f;
    for (int i = t; i < nea; i += stride) s += ea[i];
    #pragma unroll
    for (int o = 16; o; o >>= 1) s += __shfl_xor_sync(0xffffffffu, s, o);
    __shared__ float sdata[8];
    if ((threadIdx.x & 31) == 0) sdata[threadIdx.x >> 5] = s;
    __syncthreads();
    if (threadIdx.x < 8) {
        float v = sdata[threadIdx.x];
        #pragma unroll
        for (int o = 4; o; o >>= 1) v += __shfl_xor_sync(0xffu, v, o);
        if (threadIdx.x == 0) g_partial[blockIdx.x] = v;
    }
    const int e4 = E >> 2;
    for (int i = t; i < e4; i += stride) {
        int4 d4 = *(const int4*)&ei[E + i * 4];
        atomicAdd(&g_deg[d4.x], 1);
        atomicAdd(&g_deg[d4.y], 1);
        atomicAdd(&g_deg[d4.z], 1);
        atomicAdd(&g_deg[d4.w], 1);
    }
    if (t < (E & 3)) atomicAdd(&g_deg[ei[E + e4 * 4 + t]], 1);
}

// ---------------- single-block: ea-mean + scalars, exclusive scan over (deg+1) -------
// Reserves slot start[i] for node i's self-loop: cursor starts at start[i]+1.
__global__ void __launch_bounds__(1024) scan_kernel(const float* __restrict__ We1,
                                                    const float* __restrict__ ae1,
                                                    const float* __restrict__ We2,
                                                    const float* __restrict__ ae2,
                                                    int H, int C, float invE, int N) {
    __shared__ int sh[1024];
    __shared__ float sf[16];
    const int tid = threadIdx.x;
    if (tid < 512) {
        float v = g_partial[tid];
        #pragma unroll
        for (int o = 16; o; o >>= 1) v += __shfl_xor_sync(0xffffffffu, v, o);
        if ((tid & 31) == 0) sf[tid >> 5] = v;
    }
    __syncthreads();
    if (tid == 0) {
        float tot = 0.f;
        #pragma unroll
        for (int k = 0; k < 16; k++) tot += sf[k];
        float c1 = 0.f;
        for (int k = 0; k < H; k++) c1 += We1[k] * ae1[k];
        float c2 = 0.f;
        for (int k = 0; k < C; k++) c2 += We2[k] * ae2[k];
        g_scal[0] = c1;
        g_scal[2] = c2;
        g_scal[4] = tot * invE;   // mean edge attr (self-loop fill value)
    }
    __syncthreads();
    const int chunk = (((N + 1023) / 1024) + 3) & ~3;   // multiple of 4
    const int b = tid * chunk;
    const int e = min(b + chunk, N);
    int s = 0;
    if (b < N) {
        int i = b;
        for (; i + 3 < e; i += 4) {
            int4 v = *(const int4*)&g_deg[i];
            s += v.x + v.y + v.z + v.w + 4;
        }
        for (; i < e; i++) s += g_deg[i] + 1;
    }
    sh[tid] = s;
    __syncthreads();
    #pragma unroll
    for (int off = 1; off < 1024; off <<= 1) {
        int v = (tid >= off) ? sh[tid - off] : 0;
        __syncthreads();
        sh[tid] += v;
        __syncthreads();
    }
    if (b < N) {
        int run = (tid > 0) ? sh[tid - 1] : 0;
        int i = b;
        for (; i + 3 < e; i += 4) {
            int4 v = *(const int4*)&g_deg[i];
            int4 st = make_int4(run,
                                run + v.x + 1,
                                run + v.x + v.y + 2,
                                run + v.x + v.y + v.z + 3);
            *(int4*)&g_start[i] = st;
            int4 cu = make_int4(st.x + 1, st.y + 1, st.z + 1, st.w + 1);
            *(int4*)&g_cursor[i] = cu;
            run += v.x + v.y + v.z + v.w + 4;
        }
        for (; i < e; i++) {
            g_start[i] = run; g_cursor[i] = run + 1;
            run += g_deg[i] + 1;
        }
        if (e == N) g_start[N] = run;
    }
}

// ---------------- scatter edges into dst-sorted order (8 edges/thread) ---------------
// Self-loops go into the reserved slot start[i] with a PLAIN store (no atomic).
__global__ void sort_kernel(const int* __restrict__ ei, const float* __restrict__ ea,
                            int E, int N) {
    int t = blockIdx.x * blockDim.x + threadIdx.x;
    int eB = (E + 7) >> 3;
    int nB = (N + 3) >> 2;
    if (t < eB) {
        int q = t * 8;
        if (q + 7 < E && ((E & 7) == 0)) {
            int4 sa = *(const int4*)&ei[q];
            int4 sb = *(const int4*)&ei[q + 4];
            int4 da = *(const int4*)&ei[E + q];
            int4 db = *(const int4*)&ei[E + q + 4];
            float4 aa = *(const float4*)&ea[q];
            float4 ab = *(const float4*)&ea[q + 4];
            int p0 = atomicAdd(&g_cursor[da.x], 1);
            int p1 = atomicAdd(&g_cursor[da.y], 1);
            int p2 = atomicAdd(&g_cursor[da.z], 1);
            int p3 = atomicAdd(&g_cursor[da.w], 1);
            int p4 = atomicAdd(&g_cursor[db.x], 1);
            int p5 = atomicAdd(&g_cursor[db.y], 1);
            int p6 = atomicAdd(&g_cursor[db.z], 1);
            int p7 = atomicAdd(&g_cursor[db.w], 1);
            g_sedge[p0] = make_int2(sa.x, __float_as_int(aa.x));
            g_sedge[p1] = make_int2(sa.y, __float_as_int(aa.y));
            g_sedge[p2] = make_int2(sa.z, __float_as_int(aa.z));
            g_sedge[p3] = make_int2(sa.w, __float_as_int(aa.w));
            g_sedge[p4] = make_int2(sb.x, __float_as_int(ab.x));
            g_sedge[p5] = make_int2(sb.y, __float_as_int(ab.y));
            g_sedge[p6] = make_int2(sb.z, __float_as_int(ab.z));
            g_sedge[p7] = make_int2(sb.w, __float_as_int(ab.w));
        } else {
            for (int k = 0; k < 8 && q + k < E; k++) {
                int d = ei[E + q + k];
                int pos = atomicAdd(&g_cursor[d], 1);
                g_sedge[pos] = make_int2(ei[q + k], __float_as_int(ea[q + k]));
            }
        }
    } else if (t < eB + nB) {
        int i0 = (t - eB) * 4;
        float mean = g_scal[4];
        int4 st = *(const int4*)&g_start[i0];   // i0 is 4-aligned by construction
        int sarr[4] = {st.x, st.y, st.z, st.w};
        for (int k = 0; k < 4 && i0 + k < N; k++)
            g_sedge[sarr[k]] = make_int2(i0 + k, __float_as_int(mean));
    }
}

// ---------------- SGEMM via tensor cores: h1 = x[M,128] @ W1[128,64] -----------------
// mma.sync.m16n8k8 tf32; tile 128(M) x 64(N) per block, 8 warps (one m16 band each).
// tf32 conversion happens once at smem staging. fp16 h1 out + fused attention logits.
__global__ void __launch_bounds__(256) gemm1_kernel(const float* __restrict__ x,
                                                    const float* __restrict__ W,
                                                    const float* __restrict__ att_s,
                                                    const float* __restrict__ att_d, int M) {
    __shared__ uint32_t Xs[128][36];   // stride 36 ≡ 4 mod 32 -> conflict-free A frags
    __shared__ uint32_t Ws[32][72];    // stride 72 ≡ 8 mod 32 -> conflict-free B frags
    const int tid = threadIdx.x;
    const int warp = tid >> 5;        // 0..7, m-band rows 16*warp..16*warp+15
    const int lane = tid & 31;
    const int qr = lane >> 2;         // 0..7
    const int qc = lane & 3;          // 0..3
    const int m0 = blockIdx.x * 128;
    float d[8][4];
    #pragma unroll
    for (int t = 0; t < 8; t++)
        #pragma unroll
        for (int j = 0; j < 4; j++) d[t][j] = 0.f;

    for (int k0 = 0; k0 < 128; k0 += 32) {
        // stage X chunk: 128 rows x 32 k (1024 float4, 4 per thread), cvt to tf32
        #pragma unroll
        for (int it = 0; it < 4; it++) {
            int f = it * 256 + tid;           // 0..1023
            int row = f >> 3;
            int c4 = (f & 7) * 4;
            float4 v = make_float4(0.f, 0.f, 0.f, 0.f);
            int gr = m0 + row;
            if (gr < M) v = *(const float4*)&x[(size_t)gr * 128 + k0 + c4];
            Xs[row][c4 + 0] = f2tf32(v.x);
            Xs[row][c4 + 1] = f2tf32(v.y);
            Xs[row][c4 + 2] = f2tf32(v.z);
            Xs[row][c4 + 3] = f2tf32(v.w);
        }
        // stage W chunk: 32 k x 64 n (512 float4, 2 per thread), cvt to tf32
        #pragma unroll
        for (int it = 0; it < 2; it++) {
            int f = it * 256 + tid;           // 0..511
            int kk = f >> 4;
            int c4 = (f & 15) * 4;
            float4 v = *(const float4*)&W[(size_t)(k0 + kk) * 64 + c4];
            Ws[kk][c4 + 0] = f2tf32(v.x);
            Ws[kk][c4 + 1] = f2tf32(v.y);
            Ws[kk][c4 + 2] = f2tf32(v.z);
            Ws[kk][c4 + 3] = f2tf32(v.w);
        }
        __syncthreads();
        #pragma unroll
        for (int ks = 0; ks < 4; ks++) {
            const int kb = ks * 8;
            uint32_t a0 = Xs[warp * 16 + qr][kb + qc];
            uint32_t a1 = Xs[warp * 16 + qr + 8][kb + qc];
            uint32_t a2 = Xs[warp * 16 + qr][kb + qc + 4];
            uint32_t a3 = Xs[warp * 16 + qr + 8][kb + qc + 4];
            #pragma unroll
            for (int t = 0; t < 8; t++) {
                uint32_t b0 = Ws[kb + qc][t * 8 + qr];
                uint32_t b1 = Ws[kb + qc + 4][t * 8 + qr];
                mma_tf32(d[t], a0, a1, a2, a3, b0, b1);
            }
        }
        __syncthreads();
    }
    // epilogue: rows r1 = m0+16w+qr, r2 = r1+8; cols t*8 + qc*2 + {0,1}
    const int r1 = m0 + warp * 16 + qr;
    const int r2 = r1 + 8;
    float pas1 = 0.f, pad1 = 0.f, pas2 = 0.f, pad2 = 0.f;
    #pragma unroll
    for (int t = 0; t < 8; t++) {
        int col = t * 8 + qc * 2;
        float2 asv = *(const float2*)&att_s[col];
        float2 adv = *(const float2*)&att_d[col];
        if (r1 < M) g_h1h[(size_t)r1 * 32 + (col >> 1)] = __floats2half2_rn(d[t][0], d[t][1]);
        if (r2 < M) g_h1h[(size_t)r2 * 32 + (col >> 1)] = __floats2half2_rn(d[t][2], d[t][3]);
        pas1 += d[t][0] * asv.x + d[t][1] * asv.y;
        pad1 += d[t][0] * adv.x + d[t][1] * adv.y;
        pas2 += d[t][2] * asv.x + d[t][3] * asv.y;
        pad2 += d[t][2] * adv.x + d[t][3] * adv.y;
    }
    // reduce across the 4 lanes of each row-quad (xor 1, 2 stays within the quad)
    #pragma unroll
    for (int o = 1; o <= 2; o <<= 1) {
        pas1 += __shfl_xor_sync(0xffffffffu, pas1, o);
        pad1 += __shfl_xor_sync(0xffffffffu, pad1, o);
        pas2 += __shfl_xor_sync(0xffffffffu, pas2, o);
        pad2 += __shfl_xor_sync(0xffffffffu, pad2, o);
    }
    if (qc == 0) {
        if (r1 < M) { g_as1[r1] = pas1; g_ad1[r1] = pad1; }
        if (r2 < M) { g_as1[r2] = pas2; g_ad1[r2] = pad2; }
    }
}

// ---------------- layer-1 aggregation: 4 nodes/warp, 8-edge unroll, fp16 gathers -----
__global__ void aggr1_kernel(const float* __restrict__ bias1, const float* __restrict__ W2,
                             const float* __restrict__ as2, const float* __restrict__ ad2,
                             int N) {
    int gwarp = (blockIdx.x * blockDim.x + threadIdx.x) >> 5;
    int lane = threadIdx.x & 31;
    int g = lane & 7;                     // position within the 8-lane node group
    int node = gwarp * 4 + (lane >> 3);
    bool valid = node < N;
    const unsigned gmask = 0xFFu << (lane & 24);   // this group's 8 lanes
    const float c1 = g_scal[0];
    const int beg = valid ? g_start[node] : 0;
    const int end = valid ? g_start[node + 1] : 0;
    const float add = valid ? g_ad1[node] : 0.f;
    float2 a0 = make_float2(0.f, 0.f), a1 = make_float2(0.f, 0.f);
    float2 a2 = make_float2(0.f, 0.f), a3 = make_float2(0.f, 0.f);
    float dsum = 0.f;
    int i = beg;
    #define ACC1(hh, ww) { \
        float2 f0 = __half22float2(*(const __half2*)&hh.x); \
        float2 f1 = __half22float2(*(const __half2*)&hh.y); \
        float2 f2 = __half22float2(*(const __half2*)&hh.z); \
        float2 f3 = __half22float2(*(const __half2*)&hh.w); \
        a0.x += ww * f0.x; a0.y += ww * f0.y; \
        a1.x += ww * f1.x; a1.y += ww * f1.y; \
        a2.x += ww * f2.x; a2.y += ww * f2.y; \
        a3.x += ww * f3.x; a3.y += ww * f3.y; }
    for (; i + 8 <= end; i += 8) {
        int2 eg = g_sedge[i + g];          // coalesced: 8 lanes cover 64B
        float lg = g_as1[eg.x] + add + __int_as_float(eg.y) * c1;
        lg = lg > 0.f ? lg : 0.2f * lg;
        float wg = __expf(lg);
        #pragma unroll
        for (int j = 0; j < 8; j++) {
            int   sj = __shfl_sync(gmask, eg.x, j, 8);
            float wj = __shfl_sync(gmask, wg, j, 8);
            uint4 h = *(const uint4*)&g_h1h[(size_t)sj * 32 + 4 * g];
            ACC1(h, wj)
            dsum += wj;
        }
    }
    {
        int rem = end - i;
        if (rem > 0) {
            int2 eg = (g < rem) ? g_sedge[i + g] : make_int2(0, 0);
            float wg = 0.f;
            if (g < rem) {
                float lg = g_as1[eg.x] + add + __int_as_float(eg.y) * c1;
                lg = lg > 0.f ? lg : 0.2f * lg;
                wg = __expf(lg);
            }
            for (int j = 0; j < rem; j++) {
                int   sj = __shfl_sync(gmask, eg.x, j, 8);
                float wj = __shfl_sync(gmask, wg, j, 8);
                uint4 h = *(const uint4*)&g_h1h[(size_t)sj * 32 + 4 * g];
                ACC1(h, wj)
                dsum += wj;
            }
        }
    }
    #undef ACC1
    float inv = 1.f / (dsum + 1e-16f);
    // fused: bias + relu + W2 projection + layer-2 logit coefficients
    float4 ba = *(const float4*)&bias1[g * 8];
    float4 bb = *(const float4*)&bias1[g * 8 + 4];
    float v0 = fmaxf(a0.x * inv + ba.x, 0.f);
    float v1 = fmaxf(a0.y * inv + ba.y, 0.f);
    float v2 = fmaxf(a1.x * inv + ba.z, 0.f);
    float v3 = fmaxf(a1.y * inv + ba.w, 0.f);
    float v4 = fmaxf(a2.x * inv + bb.x, 0.f);
    float v5 = fmaxf(a2.y * inv + bb.y, 0.f);
    float v6 = fmaxf(a3.x * inv + bb.z, 0.f);
    float v7 = fmaxf(a3.y * inv + bb.w, 0.f);
    // W2 rows g*8 .. g*8+7 of [64,2]
    float4 wa = *(const float4*)&W2[g * 16];
    float4 wb = *(const float4*)&W2[g * 16 + 4];
    float4 wc = *(const float4*)&W2[g * 16 + 8];
    float4 wd = *(const float4*)&W2[g * 16 + 12];
    float s0 = v0 * wa.x + v1 * wa.z + v2 * wb.x + v3 * wb.z
             + v4 * wc.x + v5 * wc.z + v6 * wd.x + v7 * wd.z;
    float s1 = v0 * wa.y + v1 * wa.w + v2 * wb.y + v3 * wb.w
             + v4 * wc.y + v5 * wc.w + v6 * wd.y + v7 * wd.w;
    #pragma unroll
    for (int o = 4; o; o >>= 1) {
        s0 += __shfl_xor_sync(0xffffffffu, s0, o);
        s1 += __shfl_xor_sync(0xffffffffu, s1, o);
    }
    if (valid && g == 0) {
        g_node2[node] = make_float4(s0, s1,
                                    s0 * as2[0] + s1 * as2[1],
                                    s0 * ad2[0] + s1 * ad2[1]);
    }
}

// ---------------- layer-2 aggregation + log_softmax (4 lanes/node, 2-way unroll) -----
__global__ void aggr2_kernel(const float* __restrict__ bias2, float* __restrict__ out, int N) {
    int t = blockIdx.x * blockDim.x + threadIdx.x;
    int node = t >> 2;
    int sub = t & 3;
    bool valid = node < N;
    const float c2 = g_scal[2];
    const float add = valid ? g_node2[node].w : 0.f;
    const int beg = valid ? g_start[node] : 0;
    const int end = valid ? g_start[node + 1] : 0;
    float a0 = 0.f, a1 = 0.f, ds = 0.f;
    int i = beg + sub;
    while (i + 4 < end) {
        int2 eA = g_sedge[i];
        int2 eB = g_sedge[i + 4];
        float atA = __int_as_float(eA.y);
        float atB = __int_as_float(eB.y);
        float4 nA = g_node2[eA.x];
        float4 nB = g_node2[eB.x];
        float lgA = nA.z + add + atA * c2; lgA = lgA > 0.f ? lgA : 0.2f * lgA;
        float lgB = nB.z + add + atB * c2; lgB = lgB > 0.f ? lgB : 0.2f * lgB;
        float wA = __expf(lgA), wB = __expf(lgB);
        a0 += wA * nA.x + wB * nB.x;
        a1 += wA * nA.y + wB * nB.y;
        ds += wA + wB;
        i += 8;
    }
    if (i < end) {
        int2 eA = g_sedge[i];
        float atA = __int_as_float(eA.y);
        float4 nA = g_node2[eA.x];
        float lgA = nA.z + add + atA * c2; lgA = lgA > 0.f ? lgA : 0.2f * lgA;
        float wA = __expf(lgA);
        a0 += wA * nA.x; a1 += wA * nA.y; ds += wA;
    }
    #pragma unroll
    for (int o = 1; o <= 2; o <<= 1) {
        a0 += __shfl_xor_sync(0xffffffffu, a0, o);
        a1 += __shfl_xor_sync(0xffffffffu, a1, o);
        ds += __shfl_xor_sync(0xffffffffu, ds, o);
    }
    if (valid && sub == 0) {
        float inv = 1.f / (ds + 1e-16f);
        float o0 = a0 * inv + bias2[0];
        float o1 = a1 * inv + bias2[1];
        float m = fmaxf(o0, o1);
        float z = logf(expf(o0 - m) + expf(o1 - m));
        out[2 * node] = o0 - m - z;
        out[2 * node + 1] = o1 - m - z;
    }
}

// ---------------- host launcher ----------------
extern "C" void kernel_launch(void* const* d_in, const int* in_sizes, int n_in,
                              void* d_out, int out_size) {
    const float* x   = (const float*)d_in[0];
    const int*   ei  = (const int*)d_in[1];
    const float* ea  = (const float*)d_in[2];
    const float* W1  = (const float*)d_in[3];
    const float* as1 = (const float*)d_in[4];
    const float* ad1 = (const float*)d_in[5];
    const float* We1 = (const float*)d_in[6];
    const float* ae1 = (const float*)d_in[7];
    const float* b1  = (const float*)d_in[8];
    const float* W2  = (const float*)d_in[9];
    const float* as2 = (const float*)d_in[10];
    const float* ad2 = (const float*)d_in[11];
    const float* We2 = (const float*)d_in[12];
    const float* ae2 = (const float*)d_in[13];
    const float* b2  = (const float*)d_in[14];
    float* out = (float*)d_out;

    const int H   = in_sizes[4];          // 64
    const int Fin = in_sizes[3] / H;      // 128
    const int N   = in_sizes[0] / Fin;    // 100000
    const int E   = in_sizes[1] / 2;      // 1600000
    const int C   = in_sizes[10];         // 2
    const int nea = in_sizes[2];          // E * ED

    const int T = 256;
    const int eB = (E + 7) >> 3;
    const int nB = (N + 3) >> 2;

    void* deg_ptr = nullptr;
    cudaGetSymbolAddress(&deg_ptr, g_deg);

    // Fork: the ENTIRE preprocessing + CSR-sort pipeline is independent of the
    // GEMM (w computed inside aggr1), so it all overlaps on a side stream.
    cudaStream_t s_pre;
    cudaEvent_t ev_fork, ev_join;
    cudaStreamCreateWithFlags(&s_pre, cudaStreamNonBlocking);
    cudaEventCreateWithFlags(&ev_fork, cudaEventDisableTiming);
    cudaEventCreateWithFlags(&ev_join, cudaEventDisableTiming);

    cudaEventRecord(ev_fork, 0);
    cudaStreamWaitEvent(s_pre, ev_fork, 0);

    // side stream: memset(deg) -> prehist -> scan(+scalars) -> sort
    cudaMemsetAsync(deg_ptr, 0, (size_t)N * sizeof(int), s_pre);
    prehist_kernel<<<512, T, 0, s_pre>>>(ea, nea, ei, E);
    scan_kernel<<<1, 1024, 0, s_pre>>>(We1, ae1, We2, ae2, H, C, 1.0f / (float)E, N);
    sort_kernel<<<(eB + nB + T - 1) / T, T, 0, s_pre>>>(ei, ea, E, N);
    cudaEventRecord(ev_join, s_pre);

    // main stream: gemm runs concurrently with the whole chain above
    gemm1_kernel<<<(N + 127) / 128, 256>>>(x, W1, as1, ad1, N);

    cudaStreamWaitEvent((cudaStream_t)0, ev_join, 0);

    aggr1_kernel<<<((N + 3) / 4 * 32 + T - 1) / T, T>>>(b1, W2, as2, ad2, N);
    aggr2_kernel<<<(N * 4 + T - 1) / T, T>>>(b2, out, N);

    cudaEventDestroy(ev_fork);
    cudaEventDestroy(ev_join);
    cudaStreamDestroy(s_pre);
}